// round 1
// baseline (speedup 1.0000x reference)
#include <cuda_runtime.h>
#include <math.h>

// Problem: x is 4096x4096 fp32 = 16,777,216 elements -> 262,144 blocks of 64.
#define MAXB   262144          // max number of 64-elem blocks supported
#define MAXGA  2048            // max partial-reduction entries (MAXB / 128)

// Scratch (device globals: no allocation allowed)
__device__ float  g_scales[MAXB];
__device__ float4 g_info[MAXB];     // {s, 1/s (RN), deq_scale, 0}
__device__ float  g_pmin[MAXGA];
__device__ float  g_pmax[MAXGA];
__device__ float  g_smin;
__device__ float  g_smax;

// Branchless insertion of v into descending top-5 (t0 >= t1 >= ... >= t4).
__device__ __forceinline__ void ins5(float v, float& t0, float& t1, float& t2,
                                     float& t3, float& t4) {
    float hi, lo;
    hi = fmaxf(t0, v); lo = fminf(t0, v); t0 = hi; v = lo;
    hi = fmaxf(t1, v); lo = fminf(t1, v); t1 = hi; v = lo;
    hi = fmaxf(t2, v); lo = fminf(t2, v); t2 = hi; v = lo;
    hi = fmaxf(t3, v); lo = fminf(t3, v); t3 = hi; v = lo;
    t4 = fmaxf(t4, v);
}

// ---------------------------------------------------------------------------
// Kernel A: per-block 95th-percentile scale (needs 4th & 5th largest |x| of 64)
// 128 threads per CTA, one 64-elem block per thread, data staged through
// padded shared memory (stride 17 float4 = 68 words -> conflict-free vec4).
// Also produces per-CTA min/max partials of the scales.
// ---------------------------------------------------------------------------
__global__ void __launch_bounds__(128) kA(const float4* __restrict__ in4,
                                          int n4, int num_blocks) {
    __shared__ float4 sm[128 * 17];
    __shared__ float  rmin[128];
    __shared__ float  rmax[128];

    const int tid = threadIdx.x;
    const long long base4 = (long long)blockIdx.x * 2048;  // 128 blocks * 16 f4

    #pragma unroll
    for (int k = 0; k < 16; k++) {
        int f = k * 128 + tid;
        long long g4 = base4 + f;
        float4 v = (g4 < (long long)n4) ? in4[g4] : make_float4(0.f, 0.f, 0.f, 0.f);
        sm[(f >> 4) * 17 + (f & 15)] = v;
    }
    __syncthreads();

    float t0 = 0.f, t1 = 0.f, t2 = 0.f, t3 = 0.f, t4 = 0.f;
    #pragma unroll
    for (int j = 0; j < 16; j++) {
        float4 v = sm[tid * 17 + j];
        ins5(fabsf(v.x), t0, t1, t2, t3, t4);
        ins5(fabsf(v.y), t0, t1, t2, t3, t4);
        ins5(fabsf(v.z), t0, t1, t2, t3, t4);
        ins5(fabsf(v.w), t0, t1, t2, t3, t4);
    }

    // jnp.quantile linear: index = fp32(0.95*63) = 59.849998474...,
    // frac = index - 59 (exact). result = a[59]*(1-frac) + a[60]*frac.
    // a[59] = 5th largest = t4, a[60] = 4th largest = t3.
    const float FRAC = 0.95f * 63.0f - 59.0f;   // fp32 constant-folded
    const float OMF  = 1.0f - FRAC;
    float s = __fadd_rn(__fmul_rn(t4, OMF), __fmul_rn(t3, FRAC));
    s = fmaxf(s, 1e-8f);

    long long b = (long long)blockIdx.x * 128 + tid;
    bool valid = (b < (long long)num_blocks);
    if (valid) g_scales[b] = s;

    rmin[tid] = valid ? s : 3.402823466e38f;
    rmax[tid] = valid ? s : 0.0f;
    __syncthreads();
    #pragma unroll
    for (int off = 64; off > 0; off >>= 1) {
        if (tid < off) {
            rmin[tid] = fminf(rmin[tid], rmin[tid + off]);
            rmax[tid] = fmaxf(rmax[tid], rmax[tid + off]);
        }
        __syncthreads();
    }
    if (tid == 0) {
        g_pmin[blockIdx.x] = rmin[0];
        g_pmax[blockIdx.x] = rmax[0];
    }
}

// ---------------------------------------------------------------------------
// Kernel B: reduce partial min/max -> g_smin / g_smax (1 CTA, deterministic)
// ---------------------------------------------------------------------------
__global__ void __launch_bounds__(1024) kB(int np) {
    __shared__ float rmin[1024];
    __shared__ float rmax[1024];
    int t = threadIdx.x;
    float mn = 3.402823466e38f, mx = 0.0f;
    for (int i = t; i < np; i += 1024) {
        mn = fminf(mn, g_pmin[i]);
        mx = fmaxf(mx, g_pmax[i]);
    }
    rmin[t] = mn; rmax[t] = mx;
    __syncthreads();
    #pragma unroll
    for (int off = 512; off > 0; off >>= 1) {
        if (t < off) {
            rmin[t] = fminf(rmin[t], rmin[t + off]);
            rmax[t] = fmaxf(rmax[t], rmax[t + off]);
        }
        __syncthreads();
    }
    if (t == 0) { g_smin = rmin[0]; g_smax = rmax[0]; }
}

// ---------------------------------------------------------------------------
// Kernel C: per-block finalize — 8-bit double-quant of scale + RN reciprocal.
// All expensive MUFU / IEEE-div work happens once per block here.
// ---------------------------------------------------------------------------
__global__ void __launch_bounds__(256) kC(int num_blocks) {
    int b = blockIdx.x * 256 + threadIdx.x;
    if (b >= num_blocks) return;
    float s    = g_scales[b];
    float smin = g_smin;
    float smax = g_smax;
    bool cond  = (smax > smin);
    float ss = cond ? __fdiv_rn(__fsub_rn(smax, smin), 255.0f) : 1.0f;
    float qv = 0.0f;
    if (cond) {
        qv = rintf(__fdiv_rn(__fsub_rn(s, smin), ss));  // rintf = half-even = jnp.round
        qv = fminf(fmaxf(qv, 0.0f), 255.0f);
    }
    float deq = __fmul_rn(qv, ss);   // NOTE: smin deliberately dropped (matches ref)
    float r   = __frcp_rn(s);        // correctly-rounded reciprocal for Markstein div
    g_info[b] = make_float4(s, r, deq, 0.0f);
}

// ---------------------------------------------------------------------------
// Kernel D: main dequant pass. Bit-exact x/s via Markstein step, nearest FP4
// level with argmin tie semantics, times dequantized scale.
// ---------------------------------------------------------------------------
__device__ __forceinline__ float qd1(float x, float s, float r, float deq) {
    // Correctly-rounded quotient q = RN(x/s): r = RN(1/s); one residual FMA step.
    float q0 = __fmul_rn(x, r);
    float e  = __fmaf_rn(-s, q0, x);
    float q  = __fmaf_rn(e, r, q0);

    float a = fabsf(q);
    // Table [-3,-2,-1.5,-1,-0.75,0,0.75,1,1.5,2,3]; midpoints .375/.875/1.25/1.75/2.5.
    // argmin tie -> lowest index: strict '>' for q>=0 (tie -> smaller value),
    // '>=' for q<0 (tie -> more negative value).
    int lv;
    if (!(q < 0.0f))
        lv = (a > 0.375f) + (a > 0.875f) + (a > 1.25f) + (a > 1.75f) + (a > 2.5f);
    else
        lv = (a >= 0.375f) + (a >= 0.875f) + (a >= 1.25f) + (a >= 1.75f) + (a >= 2.5f);
    // magnitudes {0, .75, 1, 1.5, 2, 3} = 0.25 * {0,3,4,6,8,12} packed as nibbles
    float mag = (float)((0x00C86430u >> (lv << 2)) & 0xFu) * 0.25f;
    float out = __fmul_rn(mag, deq);
    return (q < 0.0f) ? -out : out;
}

__global__ void __launch_bounds__(256) kD(const float4* __restrict__ in4,
                                          float4* __restrict__ out4, int n4) {
    int i = blockIdx.x * 256 + threadIdx.x;
    if (i >= n4) return;
    int b = i >> 4;                 // 16 float4 per 64-elem block
    float4 nfo = g_info[b];         // broadcast across 16 threads -> L1 hit
    float4 x   = in4[i];
    float4 o;
    o.x = qd1(x.x, nfo.x, nfo.y, nfo.z);
    o.y = qd1(x.y, nfo.x, nfo.y, nfo.z);
    o.z = qd1(x.z, nfo.x, nfo.y, nfo.z);
    o.w = qd1(x.w, nfo.x, nfo.y, nfo.z);
    out4[i] = o;
}

// Scalar tail (n % 4 != 0) — not hit for 4096x4096 but kept for safety.
__global__ void kDtail(const float* __restrict__ in, float* __restrict__ out,
                       int start, int n) {
    int i = start + blockIdx.x * blockDim.x + threadIdx.x;
    if (i >= n) return;
    int b = i >> 6;
    float4 nfo = g_info[b];
    out[i] = qd1(in[i], nfo.x, nfo.y, nfo.z);
}

extern "C" void kernel_launch(void* const* d_in, const int* in_sizes, int n_in,
                              void* d_out, int out_size) {
    const float* x = (const float*)d_in[0];
    float* out = (float*)d_out;
    int n = in_sizes[0];

    int num_blocks = (n + 63) >> 6;
    if (num_blocks > MAXB) num_blocks = MAXB;   // safety clamp (fixed shape fits)

    int gridA = (num_blocks + 127) >> 7;        // 128 blocks per CTA
    int n4 = n >> 2;

    kA<<<gridA, 128>>>((const float4*)x, n4, num_blocks);
    kB<<<1, 1024>>>(gridA);
    kC<<<(num_blocks + 255) >> 8, 256>>>(num_blocks);
    if (n4 > 0)
        kD<<<(n4 + 255) >> 8, 256>>>((const float4*)x, (float4*)out, n4);
    int tail = n & 3;
    if (tail)
        kDtail<<<1, 32>>>(x, out, n4 << 2, n);
}

// round 2
// speedup vs baseline: 1.2187x; 1.2187x over previous
#include <cuda_runtime.h>
#include <math.h>

// Problem: x is 4096x4096 fp32 = 16,777,216 elements -> 262,144 blocks of 64.
#define MAXB   262144          // max number of 64-elem blocks supported
#define MAXGA  2048            // max partial-reduction entries (MAXB / 128)

// Scratch (device globals: no allocation allowed)
__device__ float  g_scales[MAXB];
__device__ float2 g_info2[MAXB];    // {1/s (RN), deq_scale}
__device__ float  g_pmin[MAXGA];
__device__ float  g_pmax[MAXGA];
__device__ float  g_smin;
__device__ float  g_smax;
__device__ float  g_ss;            // (smax - smin)/255 (or 1.0 if smax<=smin)
__device__ int    g_cond;          // smax > smin

// Branchless insertion of v into descending top-5 (t0 >= t1 >= ... >= t4).
__device__ __forceinline__ void ins5(float v, float& t0, float& t1, float& t2,
                                     float& t3, float& t4) {
    float hi, lo;
    hi = fmaxf(t0, v); lo = fminf(t0, v); t0 = hi; v = lo;
    hi = fmaxf(t1, v); lo = fminf(t1, v); t1 = hi; v = lo;
    hi = fmaxf(t2, v); lo = fminf(t2, v); t2 = hi; v = lo;
    hi = fmaxf(t3, v); lo = fminf(t3, v); t3 = hi; v = lo;
    t4 = fmaxf(t4, v);
}

// ---------------------------------------------------------------------------
// Kernel A: per-block 95th-percentile scale (needs 4th & 5th largest |x| of 64)
// 128 threads per CTA, one 64-elem block per thread, data staged through
// padded shared memory. Also per-CTA min/max partials of the scales.
// ---------------------------------------------------------------------------
__global__ void __launch_bounds__(128) kA(const float4* __restrict__ in4,
                                          int n4, int num_blocks) {
    __shared__ float4 sm[128 * 17];
    __shared__ float  rmin[128];
    __shared__ float  rmax[128];

    const int tid = threadIdx.x;
    const long long base4 = (long long)blockIdx.x * 2048;  // 128 blocks * 16 f4

    #pragma unroll
    for (int k = 0; k < 16; k++) {
        int f = k * 128 + tid;
        long long g4 = base4 + f;
        float4 v = (g4 < (long long)n4) ? in4[g4] : make_float4(0.f, 0.f, 0.f, 0.f);
        sm[(f >> 4) * 17 + (f & 15)] = v;
    }
    __syncthreads();

    float t0 = 0.f, t1 = 0.f, t2 = 0.f, t3 = 0.f, t4 = 0.f;
    #pragma unroll
    for (int j = 0; j < 16; j++) {
        float4 v = sm[tid * 17 + j];
        ins5(fabsf(v.x), t0, t1, t2, t3, t4);
        ins5(fabsf(v.y), t0, t1, t2, t3, t4);
        ins5(fabsf(v.z), t0, t1, t2, t3, t4);
        ins5(fabsf(v.w), t0, t1, t2, t3, t4);
    }

    // jnp.quantile linear: index = fp32(0.95*63), frac = index - 59.
    // result = a[59]*(1-frac) + a[60]*frac; a[59]=5th largest=t4, a[60]=4th=t3.
    const float FRAC = 0.95f * 63.0f - 59.0f;
    const float OMF  = 1.0f - FRAC;
    float s = __fadd_rn(__fmul_rn(t4, OMF), __fmul_rn(t3, FRAC));
    s = fmaxf(s, 1e-8f);

    long long b = (long long)blockIdx.x * 128 + tid;
    bool valid = (b < (long long)num_blocks);
    if (valid) g_scales[b] = s;

    rmin[tid] = valid ? s : 3.402823466e38f;
    rmax[tid] = valid ? s : 0.0f;
    __syncthreads();
    #pragma unroll
    for (int off = 64; off > 0; off >>= 1) {
        if (tid < off) {
            rmin[tid] = fminf(rmin[tid], rmin[tid + off]);
            rmax[tid] = fmaxf(rmax[tid], rmax[tid + off]);
        }
        __syncthreads();
    }
    if (tid == 0) {
        g_pmin[blockIdx.x] = rmin[0];
        g_pmax[blockIdx.x] = rmax[0];
    }
}

// ---------------------------------------------------------------------------
// Kernel B: reduce partial min/max -> g_smin/g_smax, and precompute the
// scale-of-scales ss (uniform across all blocks) once.
// ---------------------------------------------------------------------------
__global__ void __launch_bounds__(1024) kB(int np) {
    __shared__ float rmin[1024];
    __shared__ float rmax[1024];
    int t = threadIdx.x;
    float mn = 3.402823466e38f, mx = 0.0f;
    for (int i = t; i < np; i += 1024) {
        mn = fminf(mn, g_pmin[i]);
        mx = fmaxf(mx, g_pmax[i]);
    }
    rmin[t] = mn; rmax[t] = mx;
    __syncthreads();
    #pragma unroll
    for (int off = 512; off > 0; off >>= 1) {
        if (t < off) {
            rmin[t] = fminf(rmin[t], rmin[t + off]);
            rmax[t] = fmaxf(rmax[t], rmax[t + off]);
        }
        __syncthreads();
    }
    if (t == 0) {
        float smin = rmin[0], smax = rmax[0];
        g_smin = smin; g_smax = smax;
        int cond = (smax > smin);
        g_cond = cond;
        g_ss = cond ? __fdiv_rn(__fsub_rn(smax, smin), 255.0f) : 1.0f;
    }
}

// ---------------------------------------------------------------------------
// Kernel C: per-block finalize — 8-bit double-quant of scale + RN reciprocal.
// ---------------------------------------------------------------------------
__global__ void __launch_bounds__(256) kC(int num_blocks) {
    int b = blockIdx.x * 256 + threadIdx.x;
    if (b >= num_blocks) return;
    float s    = g_scales[b];
    float smin = g_smin;
    float ss   = g_ss;
    float qv = 0.0f;
    if (g_cond) {
        qv = rintf(__fdiv_rn(__fsub_rn(s, smin), ss));  // half-even, as jnp.round
        qv = fminf(fmaxf(qv, 0.0f), 255.0f);
    }
    float deq = __fmul_rn(qv, ss);   // NOTE: smin deliberately dropped (matches ref)
    float r   = __frcp_rn(s);        // correctly-rounded reciprocal
    g_info2[b] = make_float2(r, deq);
}

// ---------------------------------------------------------------------------
// Kernel D: main dequant pass — 8 instrs/element via fp32 bit-grid rounding.
// Magnitude levels {0.75,1,1.5,2,3} are exactly the 1-mantissa-bit fp32 grid:
// clamp |q| to [0.75,3], add 0x001FFFFF (round-half-down = positive argmin tie
// rule), mask to 0xFFC00000. Zero level via |q|>0.375. Sign via one LOP3.
// ---------------------------------------------------------------------------
__device__ __forceinline__ float qd1(float x, float r, float deq) {
    float q = __fmul_rn(x, r);
    float a = fabsf(q);
    float m = fminf(fmaxf(a, 0.75f), 3.0f);
    unsigned u = __float_as_uint(m) + 0x001FFFFFu;
    u &= 0xFFC00000u;
    float mag = (a > 0.375f) ? __uint_as_float(u) : 0.0f;
    float v = __fmul_rn(mag, deq);
    return __uint_as_float(__float_as_uint(v) |
                           (__float_as_uint(q) & 0x80000000u));
}

__global__ void __launch_bounds__(256) kD(const float4* __restrict__ in4,
                                          float4* __restrict__ out4, int n4) {
    int base = blockIdx.x * 1024 + threadIdx.x;
    #pragma unroll
    for (int k = 0; k < 4; k++) {
        int i = base + k * 256;
        if (i < n4) {
            int b = i >> 4;                 // 16 float4 per 64-elem block
            float2 nfo = g_info2[b];        // broadcast across 16 threads
            float4 x = in4[i];
            float4 o;
            o.x = qd1(x.x, nfo.x, nfo.y);
            o.y = qd1(x.y, nfo.x, nfo.y);
            o.z = qd1(x.z, nfo.x, nfo.y);
            o.w = qd1(x.w, nfo.x, nfo.y);
            __stcs(&out4[i], o);            // stream out: keep x resident in L2
        }
    }
}

// Scalar tail (n % 4 != 0) — not hit for 4096x4096 but kept for safety.
__global__ void kDtail(const float* __restrict__ in, float* __restrict__ out,
                       int start, int n) {
    int i = start + blockIdx.x * blockDim.x + threadIdx.x;
    if (i >= n) return;
    int b = i >> 6;
    float2 nfo = g_info2[b];
    out[i] = qd1(in[i], nfo.x, nfo.y);
}

extern "C" void kernel_launch(void* const* d_in, const int* in_sizes, int n_in,
                              void* d_out, int out_size) {
    const float* x = (const float*)d_in[0];
    float* out = (float*)d_out;
    int n = in_sizes[0];

    int num_blocks = (n + 63) >> 6;
    if (num_blocks > MAXB) num_blocks = MAXB;   // safety clamp (fixed shape fits)

    int gridA = (num_blocks + 127) >> 7;        // 128 blocks per CTA
    int n4 = n >> 2;

    kA<<<gridA, 128>>>((const float4*)x, n4, num_blocks);
    kB<<<1, 1024>>>(gridA);
    kC<<<(num_blocks + 255) >> 8, 256>>>(num_blocks);
    if (n4 > 0)
        kD<<<(n4 + 1023) >> 10, 256>>>((const float4*)x, (float4*)out, n4);
    int tail = n & 3;
    if (tail)
        kDtail<<<1, 32>>>(x, out, n4 << 2, n);
}